// round 11
// baseline (speedup 1.0000x reference)
#include <cuda_runtime.h>
#include <cstdint>

#define BATCH 4
#define CIN   64
#define COUT  64
#define HW    224
#define NPIX  (HW * HW)          // 50176
#define KK    9
#define NBINS 10
#define KTOT  (CIN * KK)         // 576
#define KC    16
#define NCHUNK (KTOT / KC)       // 36
#define NSTAGE 4
#define TILE_M 128
#define NTILE (NPIX / TILE_M)    // 392
#define NCONV (BATCH * NTILE)    // 1568
#define Y_ELEMS (BATCH * COUT * NPIX)
#define ESTRIDE 132              // epilogue smem stride (conflict-free)

// B fragments, f16x2 pairs: [k16-step 36][nt 8][lane 32][reg 2]
__device__ uint32_t g_wfrag[36 * 512];

__device__ __forceinline__ uint32_t pack_f16x2(float lo, float hi) {
    uint32_t d;
    asm("cvt.rn.f16x2.f32 %0, %1, %2;" : "=r"(d) : "f"(hi), "f"(lo));
    return d;
}

#define MMA_F16(d, a, b) \
    asm volatile("mma.sync.aligned.m16n8k16.row.col.f32.f16.f16.f32 " \
        "{%0,%1,%2,%3}, {%4,%5,%6,%7}, {%8,%9}, {%0,%1,%2,%3};" \
        : "+f"((d)[0]), "+f"((d)[1]), "+f"((d)[2]), "+f"((d)[3]) \
        : "r"((a).x), "r"((a).y), "r"((a).z), "r"((a).w), \
          "r"((b).x), "r"((b).y))

#define CP_ASYNC4(dst, src, sz) \
    asm volatile("cp.async.ca.shared.global [%0], [%1], 4, %2;" \
        :: "r"(dst), "l"(src), "r"(sz) : "memory")
#define CP_COMMIT() asm volatile("cp.async.commit_group;" ::: "memory")
#define CP_WAIT2()  asm volatile("cp.async.wait_group 2;" ::: "memory")

__device__ __forceinline__ uint32_t smem_u32(const void* p) {
    uint32_t a;
    asm("{ .reg .u64 t; cvta.to.shared.u64 t, %1; cvt.u32.u64 %0, t; }"
        : "=r"(a) : "l"(p));
    return a;
}

// ---------------------------------------------------------------------------
// Repack W (64,576) -> m16n8k16 B-fragment order fp16; zero hist output.
// ---------------------------------------------------------------------------
__global__ void repack_w_kernel(const float* __restrict__ w,
                                float* __restrict__ out_hist) {
    int idx = blockIdx.x * blockDim.x + threadIdx.x;
    if (idx < 36 * 512) {
        int reg  = idx & 1;
        int lane = (idx >> 1) & 31;
        int nt   = (idx >> 6) & 7;
        int s    = idx >> 9;
        int n = nt * 8 + (lane >> 2);
        int k = s * 16 + (lane & 3) * 2 + reg * 8;
        float w0 = __ldg(&w[n * KTOT + k]);
        float w1 = __ldg(&w[n * KTOT + k + 1]);
        g_wfrag[idx] = pack_f16x2(w0, w1);
    }
    if (idx < CIN * NBINS) out_hist[idx] = 0.0f;
}

// ---------------------------------------------------------------------------
// Implicit-GEMM conv via mma.sync fp16; cp.async 4-stage A pipeline.
// CTA: 128 pixels x 64 couts. 8 warps: (w&3)->M 32-block, (w>>2)->N 32-block.
// A staged as raw f32 [stage][m 128][k 16] with XOR swizzle k^((m&3)<<2);
// consumers LDS.64 + pack to f16x2.
// ---------------------------------------------------------------------------
__global__ __launch_bounds__(256, 2)
void conv_mma_kernel(const float* __restrict__ x,
                     const float* __restrict__ bias,
                     float* __restrict__ y) {
    __shared__ __align__(16) union {
        float stage[NSTAGE][128][16];   // 32 KB
        float E[8448];                  // epilogue staging (33 KB)
    } sm;

    const int tid  = threadIdx.x;
    const int w    = tid >> 5;
    const int lane = tid & 31;
    const int g    = lane >> 2;
    const int klo  = lane & 3;

    const int b    = blockIdx.x / NTILE;
    const int pix0 = (blockIdx.x % NTILE) * TILE_M;
    const float* xb = x + (size_t)b * CIN * NPIX;

    // ---- producer pixel slots: rows g and g+8 of m-tile q=w ----
    const float* ptrP[2];
    unsigned tmaskP[2];
    uint32_t dbase[2];
    const uint32_t sb0 = smem_u32(&sm.stage[0][0][0]);
    const int swz = (g & 3) << 2;      // m&3 == g&3 for both halves
    #pragma unroll
    for (int half = 0; half < 2; half++) {
        int m  = w * 16 + g + half * 8;
        int pm = pix0 + m;
        int hm = pm / HW, wm = pm - hm * HW;
        ptrP[half] = xb + hm * HW + wm - (HW + 1);
        int mk = 2 | 16;
        if (hm > 0)      mk |= 1;
        if (hm + 1 < HW) mk |= 4;
        if (wm > 0)      mk |= 8;
        if (wm + 1 < HW) mk |= 32;
        unsigned tm = 0;
        #pragma unroll
        for (int t = 0; t < 9; t++) {
            int dh = t / 3, dw = t - dh * 3;
            if (((mk >> dh) & 1) && ((mk >> (3 + dw)) & 1)) tm |= 1u << t;
        }
        tmaskP[half] = tm;
        dbase[half] = sb0 + (uint32_t)m * 64;   // row base (16 floats)
    }

    // issue one chunk's cp.asyncs (8 per thread: 2 m-slots x 4 k)
    auto issue = [&](int c) {
        const uint32_t stoff = (uint32_t)(c & (NSTAGE - 1)) * 8192;
        #pragma unroll
        for (int j = 0; j < 4; j++) {
            const int k   = c * KC + klo * 4 + j;
            const int ci  = (k * 7282) >> 16;       // k/9 for k<576
            const int tap = k - 9 * ci;
            const int dh  = (tap * 11) >> 5;        // tap/3
            const int off = ci * NPIX + tap + 221 * dh;
            const uint32_t kd = (uint32_t)((klo * 4 + j) ^ swz) * 4;
            #pragma unroll
            for (int h = 0; h < 2; h++) {
                const bool ok = (tmaskP[h] >> tap) & 1u;
                const float* src = ok ? (ptrP[h] + off) : xb;
                const uint32_t sz = ok ? 4u : 0u;
                CP_ASYNC4(stoff + dbase[h] + kd, src, sz);
            }
        }
    };

    // prologue: stages 0..2 in flight
    issue(0); CP_COMMIT();
    issue(1); CP_COMMIT();
    issue(2); CP_COMMIT();

    const int wm2 = (w & 3) * 2;
    const int wn4 = (w >> 2) * 4;
    const uint2* bwp = (const uint2*)g_wfrag;

    float d[2][4][4];
    #pragma unroll
    for (int mt = 0; mt < 2; mt++)
        #pragma unroll
        for (int nt = 0; nt < 4; nt++)
            #pragma unroll
            for (int k = 0; k < 4; k++) d[mt][nt][k] = 0.0f;

    const int kk0 = (2 * klo) ^ swz;
    const int kk1 = (2 * klo + 8) ^ swz;

    #pragma unroll 4
    for (int c = 0; c < NCHUNK; c++) {
        CP_WAIT2();               // chunk c landed (2 newer groups pending)
        __syncthreads();          // visible to all warps
        if (c + 3 < NCHUNK) issue(c + 3);
        CP_COMMIT();              // empty group at tail keeps counts exact

        const float* As = &sm.stage[c & (NSTAGE - 1)][0][0];
        uint2 Bc[4];
        #pragma unroll
        for (int nt = 0; nt < 4; nt++)
            Bc[nt] = __ldg(&bwp[((c * 8 + wn4 + nt) * 32) + lane]);

        #pragma unroll
        for (int mt = 0; mt < 2; mt++) {
            const int r0 = ((wm2 + mt) * 16 + g) * 16;
            const int r1 = r0 + 128;        // +8 rows
            float2 v00 = *(const float2*)&As[r0 + kk0];
            float2 v10 = *(const float2*)&As[r1 + kk0];
            float2 v01 = *(const float2*)&As[r0 + kk1];
            float2 v11 = *(const float2*)&As[r1 + kk1];
            uint4 A;
            A.x = pack_f16x2(v00.x, v00.y);
            A.y = pack_f16x2(v10.x, v10.y);
            A.z = pack_f16x2(v01.x, v01.y);
            A.w = pack_f16x2(v11.x, v11.y);
            #pragma unroll
            for (int nt = 0; nt < 4; nt++)
                MMA_F16(d[mt][nt], A, Bc[nt]);
        }
    }

    // ---- epilogue: stage via smem for coalesced 128B stores ----
    float breg[8];
    #pragma unroll
    for (int i = 0; i < 8; i++) breg[i] = __ldg(&bias[w * 8 + i]);
    __syncthreads();                        // all stage reads done; reuse as E

    float* E = sm.E;
    const int rbase = (w & 3) * 32 + g;
    const int cbase = wn4 * 8 + klo * 2;
    #pragma unroll
    for (int mt = 0; mt < 2; mt++) {
        #pragma unroll
        for (int nt = 0; nt < 4; nt++) {
            int r0 = rbase + mt * 16;
            int c0 = cbase + nt * 8;
            E[c0 * ESTRIDE + r0]           = d[mt][nt][0];
            E[(c0 + 1) * ESTRIDE + r0]     = d[mt][nt][1];
            E[c0 * ESTRIDE + r0 + 8]       = d[mt][nt][2];
            E[(c0 + 1) * ESTRIDE + r0 + 8] = d[mt][nt][3];
        }
    }
    __syncthreads();

    float* yb = y + (size_t)b * COUT * NPIX + pix0;
    const int p4 = lane * 4;
    #pragma unroll
    for (int i = 0; i < 8; i++) {
        int co = w * 8 + i;
        float4 v = *(const float4*)&E[co * ESTRIDE + p4];
        float bv = breg[i];
        v.x += bv; v.y += bv; v.z += bv; v.w += bv;
        *(float4*)&yb[(size_t)co * NPIX + p4] = v;
    }
}

// ---------------------------------------------------------------------------
// Histogram: warp-ballot byte-SIMD separable window-sum, direct float output.
// ---------------------------------------------------------------------------
__device__ __forceinline__ unsigned zprow_calc(unsigned nib, int l) {
    unsigned nl = __shfl_sync(0xFFFFFFFFu, nib, (l == 0) ? 29 : (l - 1));
    unsigned nr = __shfl_sync(0xFFFFFFFFu, nib, (l == 27) ? 28 : ((l + 1) & 31));
    unsigned ext = ((nl >> 3) & 1u) | (nib << 1) | ((nr & 1u) << 5);
    unsigned z0 = __popc(ext & 7u);
    unsigned z1 = __popc((ext >> 1) & 7u);
    unsigned z2 = __popc((ext >> 2) & 7u);
    unsigned z3 = __popc((ext >> 3) & 7u);
    return z0 | (z1 << 8) | (z2 << 16) | (z3 << 24);
}

__global__ __launch_bounds__(256)
void hist_count_kernel(const float* __restrict__ x, const float* __restrict__ w,
                       float* __restrict__ out_hist) {
    const int bid = blockIdx.x;
    const int rc = bid & 3;
    const int c  = (bid >> 2) & 63;
    const int b  = bid >> 8;

    __shared__ int sbin[NBINS];
    const int tid = threadIdx.x;
    if (tid < NBINS) sbin[tid] = 0;

    bool anywz = false;
    #pragma unroll
    for (int k = 0; k < KK; k++) anywz |= (__ldg(&w[c * KK + k]) == 0.0f);
    __syncthreads();

    const float* xp = x + (size_t)(b * CIN + c) * NPIX;

    if (!anywz) {
        const int wd = tid >> 5, l = tid & 31;
        const int half = wd & 1, sub = wd >> 1;
        const int r0 = rc * 56 + sub * 14;
        int colb; bool ldok;
        if (l < 28)      { colb = 112 * half + 4 * l;  ldok = true; }
        else if (l == 28){ colb = 112 * half + 112;    ldok = (half == 0); }
        else if (l == 29){ colb = 112 * half - 4;      ldok = (half == 1); }
        else             { colb = 0;                   ldok = false; }

        auto vget = [&](int row) -> float4 {
            if (ldok && row >= 0 && row < HW)
                return __ldg((const float4*)(xp + row * HW + colb));
            return make_float4(1.f, 1.f, 1.f, 1.f);
        };
        auto nibof = [&](int row, float4 v) -> unsigned {
            if (!ldok || row < 0 || row >= HW) return 0xFu;
            return (v.x == 0.f ? 1u : 0u) | (v.y == 0.f ? 2u : 0u) |
                   (v.z == 0.f ? 4u : 0u) | (v.w == 0.f ? 8u : 0u);
        };

        int cnt0 = 0;
        float4 va = vget(r0 - 1);
        float4 vb = vget(r0);
        float4 vnext = vget(r0 + 1);
        unsigned zpm = zprow_calc(nibof(r0 - 1, va), l);
        unsigned zpc = zprow_calc(nibof(r0, vb), l);

        for (int r = r0; r < r0 + 14; r++) {
            float4 vd = vget(r + 2);
            unsigned zpn = zprow_calc(nibof(r + 1, vnext), l);
            unsigned z4 = zpm + zpc + zpn;   // byte-SIMD (max 9/byte)
            if (l < 28) {
                if (z4 == 0) cnt0 += 4;
                else {
                    #pragma unroll
                    for (int j = 0; j < 4; j++) {
                        unsigned bz = (z4 >> (8 * j)) & 0xFFu;
                        if (bz == 0) cnt0++;
                        else atomicAdd(&sbin[bz], 1);
                    }
                }
            }
            zpm = zpc; zpc = zpn; vnext = vd;
        }
        if (l < 28 && cnt0) atomicAdd(&sbin[0], cnt0);
    } else {
        bool wz[KK];
        #pragma unroll
        for (int k = 0; k < KK; k++) wz[k] = (__ldg(&w[c * KK + k]) == 0.0f);
        const int col = tid;
        const int r0q = rc * 56;
        if (col < HW) {
            for (int row = r0q; row < r0q + 56; row++) {
                int z = 0;
                #pragma unroll
                for (int kh = 0; kh < 3; kh++)
                    #pragma unroll
                    for (int kw = 0; kw < 3; kw++) {
                        int gy = row + kh - 1, gx = col + kw - 1;
                        bool zero = (gy < 0 || gy >= HW || gx < 0 || gx >= HW)
                            ? true
                            : (wz[kh * 3 + kw] || __ldg(&xp[gy * HW + gx]) == 0.0f);
                        z += zero ? 1 : 0;
                    }
                atomicAdd(&sbin[z], 1);
            }
        }
    }

    __syncthreads();
    if (tid < NBINS && sbin[tid])
        atomicAdd(&out_hist[c * NBINS + tid], (float)sbin[tid]);
}

// ---------------------------------------------------------------------------
extern "C" void kernel_launch(void* const* d_in, const int* in_sizes, int n_in,
                              void* d_out, int out_size) {
    const float* x    = (const float*)d_in[0];   // (4,64,224,224)
    const float* wgt  = (const float*)d_in[1];   // (64,64,3,3)
    const float* bias = (const float*)d_in[2];   // (64,)
    float* y    = (float*)d_out;
    float* hist = (float*)d_out + (size_t)Y_ELEMS;

    repack_w_kernel<<<(36 * 512 + 255) / 256, 256>>>(wgt, hist);
    conv_mma_kernel<<<NCONV, 256>>>(x, bias, y);
    hist_count_kernel<<<BATCH * CIN * 4, 256>>>(x, wgt, hist);
}

// round 12
// speedup vs baseline: 1.4665x; 1.4665x over previous
#include <cuda_runtime.h>
#include <cstdint>

#define BATCH 4
#define CIN   64
#define COUT  64
#define HW    224
#define NPIX  (HW * HW)          // 50176
#define KK    9
#define NBINS 10
#define KTOT  (CIN * KK)         // 576
#define KC    32
#define NCHUNK (KTOT / KC)       // 18
#define TILE_M 128
#define NTILE (NPIX / TILE_M)    // 392
#define NCONV (BATCH * NTILE)    // 1568
#define Y_ELEMS (BATCH * COUT * NPIX)
#define ESTRIDE 132              // epilogue smem stride (conflict-free)

// B fragments, f16x2 pairs: [k16-step 36][nt 8][lane 32][reg 2]
__device__ uint32_t g_wfrag[36 * 512];

__device__ __forceinline__ uint32_t pack_f16x2(float lo, float hi) {
    uint32_t d;
    asm("cvt.rn.f16x2.f32 %0, %1, %2;" : "=r"(d) : "f"(hi), "f"(lo));
    return d;
}

#define MMA_F16(d, a, b) \
    asm volatile("mma.sync.aligned.m16n8k16.row.col.f32.f16.f16.f32 " \
        "{%0,%1,%2,%3}, {%4,%5,%6,%7}, {%8,%9}, {%0,%1,%2,%3};" \
        : "+f"((d)[0]), "+f"((d)[1]), "+f"((d)[2]), "+f"((d)[3]) \
        : "r"((a).x), "r"((a).y), "r"((a).z), "r"((a).w), \
          "r"((b).x), "r"((b).y))

// ---------------------------------------------------------------------------
// Repack W (64,576) -> m16n8k16 B-fragment order fp16; zero hist output.
// ---------------------------------------------------------------------------
__global__ void repack_w_kernel(const float* __restrict__ w,
                                float* __restrict__ out_hist) {
    int idx = blockIdx.x * blockDim.x + threadIdx.x;
    if (idx < 36 * 512) {
        int reg  = idx & 1;
        int lane = (idx >> 1) & 31;
        int nt   = (idx >> 6) & 7;
        int s    = idx >> 9;
        int n = nt * 8 + (lane >> 2);
        int k = s * 16 + (lane & 3) * 2 + reg * 8;
        float w0 = __ldg(&w[n * KTOT + k]);
        float w1 = __ldg(&w[n * KTOT + k + 1]);
        g_wfrag[idx] = pack_f16x2(w0, w1);
    }
    if (idx < CIN * NBINS) out_hist[idx] = 0.0f;
}

// ---------------------------------------------------------------------------
// Implicit-GEMM conv via mma.sync fp16 (m16n8k16), f32 accumulate.
// 512-thread CTA: 128 pixels x 64 couts. 16 warps: (w&7)->M 16-block,
// (w>>3)->N 32-block. Each thread stages exactly ONE A fragment per chunk
// (slot mt=w&7, ks=w>>3). 32 warps/SM for latency hiding; ~16 acc regs.
// ---------------------------------------------------------------------------
struct ConvSh {
    uint4 sA[2][512];    // 16 KB: [buf][(mt*2+ks)*32+lane]
    int   tab[KTOT];
};

__global__ __launch_bounds__(512, 2)
void conv_mma_kernel(const float* __restrict__ x,
                     const float* __restrict__ bias,
                     float* __restrict__ y) {
    __shared__ __align__(16) union { ConvSh c; float E[8448]; } sm;

    uint4 (*sA)[512] = sm.c.sA;
    int*   tab   = sm.c.tab;

    const int tid  = threadIdx.x;
    const int w    = tid >> 5;      // 0..15
    const int lane = tid & 31;
    const int g    = lane >> 2;
    const int klo  = lane & 3;

    for (int i = tid; i < KTOT; i += 512) {
        int ci = i / 9, tap = i - ci * 9;
        int dh = tap / 3, dw = tap - dh * 3;
        tab[i] = (ci * NPIX + dh * HW + dw) | (tap << 24);
    }

    const int b    = blockIdx.x / NTILE;
    const int pix0 = (blockIdx.x % NTILE) * TILE_M;
    const float* xb = x + (size_t)b * CIN * NPIX;

    // ---- producer slot: m-tile mtb = w&7, k16-step ksp = w>>3 ----
    const int mtb = w & 7;
    const int ksp = w >> 3;
    const int kbp = ksp * 16 + 2 * klo;     // chunk-local k base

    const float* ptrP[2];
    unsigned tmaskP[2];
    #pragma unroll
    for (int half = 0; half < 2; half++) {
        int m  = mtb * 16 + g + half * 8;
        int pm = pix0 + m;
        int hm = pm / HW, wm = pm - hm * HW;
        ptrP[half] = xb + hm * HW + wm - (HW + 1);
        int mk = 2 | 16;
        if (hm > 0)      mk |= 1;
        if (hm + 1 < HW) mk |= 4;
        if (wm > 0)      mk |= 8;
        if (wm + 1 < HW) mk |= 32;
        unsigned tm = 0;
        #pragma unroll
        for (int t = 0; t < 9; t++) {
            int dh = t / 3, dw = t - dh * 3;
            if (((mk >> dh) & 1) && ((mk >> (3 + dw)) & 1)) tm |= 1u << t;
        }
        tmaskP[half] = tm;
    }

    __syncthreads();   // tab ready

    // stage ONE fragment (uint4) for chunk c
    auto loadA = [&](int c, uint4& S) {
        float v[2][4];
        #pragma unroll
        for (int j = 0; j < 4; j++) {
            const int koff = kbp + (j & 1) + (j >> 1) * 8;  // kb,kb+1,kb+8,kb+9
            const int e    = tab[c * KC + koff];
            const int off  = e & 0xFFFFFF;
            const int tap  = e >> 24;
            #pragma unroll
            for (int h = 0; h < 2; h++)
                v[h][j] = ((tmaskP[h] >> tap) & 1u) ? __ldg(ptrP[h] + off) : 0.0f;
        }
        S = make_uint4(pack_f16x2(v[0][0], v[0][1]), pack_f16x2(v[1][0], v[1][1]),
                       pack_f16x2(v[0][2], v[0][3]), pack_f16x2(v[1][2], v[1][3]));
    };

    const int wm1 = w & 7;          // consumer M-tile
    const int wn4 = (w >> 3) * 4;   // consumer N base (x8 couts)
    const uint2* bwp = (const uint2*)g_wfrag;

    float d[4][4];
    #pragma unroll
    for (int nt = 0; nt < 4; nt++)
        #pragma unroll
        for (int k = 0; k < 4; k++) d[nt][k] = 0.0f;

    uint4 S;
    loadA(0, S);

    for (int c = 0; c < NCHUNK; c++) {
        const int p = c & 1;
        sA[p][(mtb * 2 + ksp) * 32 + lane] = S;
        __syncthreads();
        if (c + 1 < NCHUNK) loadA(c + 1, S);

        #pragma unroll
        for (int ks = 0; ks < 2; ks++) {
            uint4 A = sA[p][(wm1 * 2 + ks) * 32 + lane];
            #pragma unroll
            for (int nt = 0; nt < 4; nt++) {
                uint2 bv = __ldg(&bwp[(((c * 2 + ks) * 8 + wn4 + nt) * 32) + lane]);
                MMA_F16(d[nt], A, bv);
            }
        }
    }

    // ---- epilogue: stage via smem for coalesced 128B stores ----
    float breg[4];
    #pragma unroll
    for (int i = 0; i < 4; i++) breg[i] = __ldg(&bias[w * 4 + i]);
    __syncthreads();                         // all smem reads done; reuse as E

    float* E = sm.E;
    const int rbase = wm1 * 16 + g;
    const int cbase = wn4 * 8 + klo * 2;
    #pragma unroll
    for (int nt = 0; nt < 4; nt++) {
        int c0 = cbase + nt * 8;
        E[c0 * ESTRIDE + rbase]           = d[nt][0];
        E[(c0 + 1) * ESTRIDE + rbase]     = d[nt][1];
        E[c0 * ESTRIDE + rbase + 8]       = d[nt][2];
        E[(c0 + 1) * ESTRIDE + rbase + 8] = d[nt][3];
    }
    __syncthreads();

    float* yb = y + (size_t)b * COUT * NPIX + pix0;
    const int p4 = lane * 4;
    #pragma unroll
    for (int i = 0; i < 4; i++) {
        int co = w * 4 + i;
        float4 v = *(const float4*)&E[co * ESTRIDE + p4];
        float bv = breg[i];
        v.x += bv; v.y += bv; v.z += bv; v.w += bv;
        *(float4*)&yb[(size_t)co * NPIX + p4] = v;
    }
}

// ---------------------------------------------------------------------------
// Histogram: warp-ballot byte-SIMD separable window-sum, direct float output.
// product(b,c,ho,wo,k)==0 iff pad || x==0 || w[0,c,k]==0.
// ---------------------------------------------------------------------------
__device__ __forceinline__ unsigned zprow_calc(unsigned nib, int l) {
    unsigned nl = __shfl_sync(0xFFFFFFFFu, nib, (l == 0) ? 29 : (l - 1));
    unsigned nr = __shfl_sync(0xFFFFFFFFu, nib, (l == 27) ? 28 : ((l + 1) & 31));
    unsigned ext = ((nl >> 3) & 1u) | (nib << 1) | ((nr & 1u) << 5);
    unsigned z0 = __popc(ext & 7u);
    unsigned z1 = __popc((ext >> 1) & 7u);
    unsigned z2 = __popc((ext >> 2) & 7u);
    unsigned z3 = __popc((ext >> 3) & 7u);
    return z0 | (z1 << 8) | (z2 << 16) | (z3 << 24);
}

__global__ __launch_bounds__(256)
void hist_count_kernel(const float* __restrict__ x, const float* __restrict__ w,
                       float* __restrict__ out_hist) {
    const int bid = blockIdx.x;
    const int rc = bid & 3;
    const int c  = (bid >> 2) & 63;
    const int b  = bid >> 8;

    __shared__ int sbin[NBINS];
    const int tid = threadIdx.x;
    if (tid < NBINS) sbin[tid] = 0;

    bool anywz = false;
    #pragma unroll
    for (int k = 0; k < KK; k++) anywz |= (__ldg(&w[c * KK + k]) == 0.0f);
    __syncthreads();

    const float* xp = x + (size_t)(b * CIN + c) * NPIX;

    if (!anywz) {
        const int wd = tid >> 5, l = tid & 31;
        const int half = wd & 1, sub = wd >> 1;
        const int r0 = rc * 56 + sub * 14;
        int colb; bool ldok;
        if (l < 28)      { colb = 112 * half + 4 * l;  ldok = true; }
        else if (l == 28){ colb = 112 * half + 112;    ldok = (half == 0); }
        else if (l == 29){ colb = 112 * half - 4;      ldok = (half == 1); }
        else             { colb = 0;                   ldok = false; }

        auto vget = [&](int row) -> float4 {
            if (ldok && row >= 0 && row < HW)
                return __ldg((const float4*)(xp + row * HW + colb));
            return make_float4(1.f, 1.f, 1.f, 1.f);
        };
        auto nibof = [&](int row, float4 v) -> unsigned {
            if (!ldok || row < 0 || row >= HW) return 0xFu;
            return (v.x == 0.f ? 1u : 0u) | (v.y == 0.f ? 2u : 0u) |
                   (v.z == 0.f ? 4u : 0u) | (v.w == 0.f ? 8u : 0u);
        };

        int cnt0 = 0;
        float4 va = vget(r0 - 1);
        float4 vb = vget(r0);
        float4 vnext = vget(r0 + 1);
        unsigned zpm = zprow_calc(nibof(r0 - 1, va), l);
        unsigned zpc = zprow_calc(nibof(r0, vb), l);

        for (int r = r0; r < r0 + 14; r++) {
            float4 vd = vget(r + 2);
            unsigned zpn = zprow_calc(nibof(r + 1, vnext), l);
            unsigned z4 = zpm + zpc + zpn;   // byte-SIMD (max 9/byte)
            if (l < 28) {
                if (z4 == 0) cnt0 += 4;
                else {
                    #pragma unroll
                    for (int j = 0; j < 4; j++) {
                        unsigned bz = (z4 >> (8 * j)) & 0xFFu;
                        if (bz == 0) cnt0++;
                        else atomicAdd(&sbin[bz], 1);
                    }
                }
            }
            zpm = zpc; zpc = zpn; vnext = vd;
        }
        if (l < 28 && cnt0) atomicAdd(&sbin[0], cnt0);
    } else {
        bool wz[KK];
        #pragma unroll
        for (int k = 0; k < KK; k++) wz[k] = (__ldg(&w[c * KK + k]) == 0.0f);
        const int col = tid;
        const int r0q = rc * 56;
        if (col < HW) {
            for (int row = r0q; row < r0q + 56; row++) {
                int z = 0;
                #pragma unroll
                for (int kh = 0; kh < 3; kh++)
                    #pragma unroll
                    for (int kw = 0; kw < 3; kw++) {
                        int gy = row + kh - 1, gx = col + kw - 1;
                        bool zero = (gy < 0 || gy >= HW || gx < 0 || gx >= HW)
                            ? true
                            : (wz[kh * 3 + kw] || __ldg(&xp[gy * HW + gx]) == 0.0f);
                        z += zero ? 1 : 0;
                    }
                atomicAdd(&sbin[z], 1);
            }
        }
    }

    __syncthreads();
    if (tid < NBINS && sbin[tid])
        atomicAdd(&out_hist[c * NBINS + tid], (float)sbin[tid]);
}

// ---------------------------------------------------------------------------
extern "C" void kernel_launch(void* const* d_in, const int* in_sizes, int n_in,
                              void* d_out, int out_size) {
    const float* x    = (const float*)d_in[0];   // (4,64,224,224)
    const float* wgt  = (const float*)d_in[1];   // (64,64,3,3)
    const float* bias = (const float*)d_in[2];   // (64,)
    float* y    = (float*)d_out;
    float* hist = (float*)d_out + (size_t)Y_ELEMS;

    repack_w_kernel<<<(36 * 512 + 255) / 256, 256>>>(wgt, hist);
    conv_mma_kernel<<<NCONV, 512>>>(x, bias, y);
    hist_count_kernel<<<BATCH * CIN * 4, 256>>>(x, wgt, hist);
}

// round 13
// speedup vs baseline: 1.7743x; 1.2099x over previous
#include <cuda_runtime.h>
#include <cstdint>

#define BATCH 4
#define CIN   64
#define COUT  64
#define HW    224
#define NPIX  (HW * HW)          // 50176
#define KK    9
#define NBINS 10
#define KTOT  (CIN * KK)         // 576
#define KC    64
#define NCHUNK (KTOT / KC)       // 9
#define TILE_M 128
#define NTILE (NPIX / TILE_M)    // 392
#define NCONV (BATCH * NTILE)    // 1568
#define Y_ELEMS (BATCH * COUT * NPIX)
#define ESTRIDE 132              // epilogue smem stride (conflict-free)

// B fragments as uint4: [spair 18][nt 8][lane 32] -> (ks0.reg0, ks0.reg1, ks1.reg0, ks1.reg1)
__device__ uint4 g_wfrag[18 * 8 * 32];

__device__ __forceinline__ uint32_t pack_f16x2(float lo, float hi) {
    uint32_t d;
    asm("cvt.rn.f16x2.f32 %0, %1, %2;" : "=r"(d) : "f"(hi), "f"(lo));
    return d;
}

#define MMA_F16(d, a, b0, b1) \
    asm volatile("mma.sync.aligned.m16n8k16.row.col.f32.f16.f16.f32 " \
        "{%0,%1,%2,%3}, {%4,%5,%6,%7}, {%8,%9}, {%0,%1,%2,%3};" \
        : "+f"((d)[0]), "+f"((d)[1]), "+f"((d)[2]), "+f"((d)[3]) \
        : "r"((a).x), "r"((a).y), "r"((a).z), "r"((a).w), \
          "r"(b0), "r"(b1))

// ---------------------------------------------------------------------------
// Repack W (64,576) -> paired m16n8k16 B-fragment order fp16; zero hist out.
//   flat idx: reg(1b) | ks(1b) | lane(5b) | nt(3b) | sp(5b)
//   n = nt*8 + (lane>>2);  k = sp*32 + ks*16 + (lane&3)*2 + reg*8
// ---------------------------------------------------------------------------
__global__ void repack_w_kernel(const float* __restrict__ w,
                                float* __restrict__ out_hist) {
    int idx = blockIdx.x * blockDim.x + threadIdx.x;
    if (idx < 18 * 8 * 32 * 4) {
        int reg  = idx & 1;
        int ks   = (idx >> 1) & 1;
        int lane = (idx >> 2) & 31;
        int nt   = (idx >> 7) & 7;
        int sp   = idx >> 10;
        int n = nt * 8 + (lane >> 2);
        int k = sp * 32 + ks * 16 + (lane & 3) * 2 + reg * 8;
        float w0 = __ldg(&w[n * KTOT + k]);
        float w1 = __ldg(&w[n * KTOT + k + 1]);
        ((uint32_t*)g_wfrag)[((sp * 8 + nt) * 32 + lane) * 4 + ks * 2 + reg] =
            pack_f16x2(w0, w1);
    }
    if (idx < CIN * NBINS) out_hist[idx] = 0.0f;
}

// ---------------------------------------------------------------------------
// Implicit-GEMM conv via mma.sync fp16 (m16n8k16), f32 accumulate.
// CTA: 128 pixels x 64 couts, 256 threads, 8 warps: (w&3)->M 32, (w>>2)->N 32.
// KC=64: 9 chunks, ONE barrier each. Producer warp w stages m-tile w's
// fragments for all 4 k16-steps of the chunk (4 x uint4 per thread).
// B loaded as uint4 pairs (8 x LDG.128 per warp per chunk).
// ---------------------------------------------------------------------------
struct ConvSh {
    uint4 sA[2][1024];   // 32 KB: [buf][(mt*4+ks)*32+lane]
    int   tab[KTOT];
};

__global__ __launch_bounds__(256, 2)
void conv_mma_kernel(const float* __restrict__ x,
                     const float* __restrict__ bias,
                     float* __restrict__ y) {
    __shared__ __align__(16) union { ConvSh c; float E[8448]; } sm;

    uint4 (*sA)[1024] = sm.c.sA;
    int*   tab = sm.c.tab;

    const int tid  = threadIdx.x;
    const int w    = tid >> 5;
    const int lane = tid & 31;
    const int g    = lane >> 2;
    const int klo  = lane & 3;

    for (int i = tid; i < KTOT; i += 256) {
        int ci = i / 9, tap = i - ci * 9;
        int dh = tap / 3, dw = tap - dh * 3;
        tab[i] = (ci * NPIX + dh * HW + dw) | (tap << 24);
    }

    const int b    = blockIdx.x / NTILE;
    const int pix0 = (blockIdx.x % NTILE) * TILE_M;
    const float* xb = x + (size_t)b * CIN * NPIX;

    // ---- producer pixel slots: rows g and g+8 of m-tile w ----
    const float* ptrP[2];
    unsigned tmaskP[2];
    #pragma unroll
    for (int half = 0; half < 2; half++) {
        int m  = w * 16 + g + half * 8;
        int pm = pix0 + m;
        int hm = pm / HW, wm = pm - hm * HW;
        ptrP[half] = xb + hm * HW + wm - (HW + 1);
        int mk = 2 | 16;
        if (hm > 0)      mk |= 1;
        if (hm + 1 < HW) mk |= 4;
        if (wm > 0)      mk |= 8;
        if (wm + 1 < HW) mk |= 32;
        unsigned tm = 0;
        #pragma unroll
        for (int t = 0; t < 9; t++) {
            int dh = t / 3, dw = t - dh * 3;
            if (((mk >> dh) & 1) && ((mk >> (3 + dw)) & 1)) tm |= 1u << t;
        }
        tmaskP[half] = tm;
    }

    __syncthreads();   // tab ready

    const int kb = 2 * klo;

    // stage 4 fragments (one per k16-step) for chunk c
    auto loadA = [&](int c, uint4* S) {
        #pragma unroll
        for (int ks = 0; ks < 4; ks++) {
            float v[2][4];
            #pragma unroll
            for (int j = 0; j < 4; j++) {
                const int koff = ks * 16 + kb + (j & 1) + (j >> 1) * 8;
                const int e    = tab[c * KC + koff];
                const int off  = e & 0xFFFFFF;
                const int tap  = e >> 24;
                #pragma unroll
                for (int h = 0; h < 2; h++)
                    v[h][j] = ((tmaskP[h] >> tap) & 1u) ? __ldg(ptrP[h] + off)
                                                        : 0.0f;
            }
            S[ks] = make_uint4(
                pack_f16x2(v[0][0], v[0][1]), pack_f16x2(v[1][0], v[1][1]),
                pack_f16x2(v[0][2], v[0][3]), pack_f16x2(v[1][2], v[1][3]));
        }
    };

    const int wm2 = (w & 3) * 2;
    const int wn4 = (w >> 2) * 4;

    float d[2][4][4];
    #pragma unroll
    for (int mt = 0; mt < 2; mt++)
        #pragma unroll
        for (int nt = 0; nt < 4; nt++)
            #pragma unroll
            for (int k = 0; k < 4; k++) d[mt][nt][k] = 0.0f;

    uint4 S[4];
    loadA(0, S);

    for (int c = 0; c < NCHUNK; c++) {
        const int p = c & 1;
        #pragma unroll
        for (int ks = 0; ks < 4; ks++)
            sA[p][(w * 4 + ks) * 32 + lane] = S[ks];
        __syncthreads();
        if (c + 1 < NCHUNK) loadA(c + 1, S);

        #pragma unroll
        for (int kp = 0; kp < 2; kp++) {           // k16-step pairs
            const int sp = c * 2 + kp;
            uint4 Bq[4];
            #pragma unroll
            for (int nt = 0; nt < 4; nt++)
                Bq[nt] = __ldg(&g_wfrag[(sp * 8 + wn4 + nt) * 32 + lane]);
            #pragma unroll
            for (int ks = 0; ks < 2; ks++) {
                uint4 A0 = sA[p][(wm2 * 4 + kp * 2 + ks) * 32 + lane];
                uint4 A1 = sA[p][((wm2 + 1) * 4 + kp * 2 + ks) * 32 + lane];
                #pragma unroll
                for (int nt = 0; nt < 4; nt++) {
                    uint32_t b0 = ks ? Bq[nt].z : Bq[nt].x;
                    uint32_t b1 = ks ? Bq[nt].w : Bq[nt].y;
                    MMA_F16(d[0][nt], A0, b0, b1);
                    MMA_F16(d[1][nt], A1, b0, b1);
                }
            }
        }
    }

    // ---- epilogue: stage via smem for coalesced 128B stores ----
    float breg[8];
    #pragma unroll
    for (int i = 0; i < 8; i++) breg[i] = __ldg(&bias[w * 8 + i]);
    __syncthreads();                         // all smem reads done; reuse as E

    float* E = sm.E;
    const int rbase = (w & 3) * 32 + g;
    const int cbase = wn4 * 8 + klo * 2;
    #pragma unroll
    for (int mt = 0; mt < 2; mt++) {
        #pragma unroll
        for (int nt = 0; nt < 4; nt++) {
            int r0 = rbase + mt * 16;
            int c0 = cbase + nt * 8;
            E[c0 * ESTRIDE + r0]           = d[mt][nt][0];
            E[(c0 + 1) * ESTRIDE + r0]     = d[mt][nt][1];
            E[c0 * ESTRIDE + r0 + 8]       = d[mt][nt][2];
            E[(c0 + 1) * ESTRIDE + r0 + 8] = d[mt][nt][3];
        }
    }
    __syncthreads();

    float* yb = y + (size_t)b * COUT * NPIX + pix0;
    const int p4 = lane * 4;
    #pragma unroll
    for (int i = 0; i < 8; i++) {
        int co = w * 8 + i;
        float4 v = *(const float4*)&E[co * ESTRIDE + p4];
        float bv = breg[i];
        v.x += bv; v.y += bv; v.z += bv; v.w += bv;
        *(float4*)&yb[(size_t)co * NPIX + p4] = v;
    }
}

// ---------------------------------------------------------------------------
// Histogram: warp-ballot byte-SIMD separable window-sum, direct float output.
// ---------------------------------------------------------------------------
__device__ __forceinline__ unsigned zprow_calc(unsigned nib, int l) {
    unsigned nl = __shfl_sync(0xFFFFFFFFu, nib, (l == 0) ? 29 : (l - 1));
    unsigned nr = __shfl_sync(0xFFFFFFFFu, nib, (l == 27) ? 28 : ((l + 1) & 31));
    unsigned ext = ((nl >> 3) & 1u) | (nib << 1) | ((nr & 1u) << 5);
    unsigned z0 = __popc(ext & 7u);
    unsigned z1 = __popc((ext >> 1) & 7u);
    unsigned z2 = __popc((ext >> 2) & 7u);
    unsigned z3 = __popc((ext >> 3) & 7u);
    return z0 | (z1 << 8) | (z2 << 16) | (z3 << 24);
}

__global__ __launch_bounds__(256)
void hist_count_kernel(const float* __restrict__ x, const float* __restrict__ w,
                       float* __restrict__ out_hist) {
    const int bid = blockIdx.x;
    const int rc = bid & 3;
    const int c  = (bid >> 2) & 63;
    const int b  = bid >> 8;

    __shared__ int sbin[NBINS];
    const int tid = threadIdx.x;
    if (tid < NBINS) sbin[tid] = 0;

    bool anywz = false;
    #pragma unroll
    for (int k = 0; k < KK; k++) anywz |= (__ldg(&w[c * KK + k]) == 0.0f);
    __syncthreads();

    const float* xp = x + (size_t)(b * CIN + c) * NPIX;

    if (!anywz) {
        const int wd = tid >> 5, l = tid & 31;
        const int half = wd & 1, sub = wd >> 1;
        const int r0 = rc * 56 + sub * 14;
        int colb; bool ldok;
        if (l < 28)      { colb = 112 * half + 4 * l;  ldok = true; }
        else if (l == 28){ colb = 112 * half + 112;    ldok = (half == 0); }
        else if (l == 29){ colb = 112 * half - 4;      ldok = (half == 1); }
        else             { colb = 0;                   ldok = false; }

        auto vget = [&](int row) -> float4 {
            if (ldok && row >= 0 && row < HW)
                return __ldg((const float4*)(xp + row * HW + colb));
            return make_float4(1.f, 1.f, 1.f, 1.f);
        };
        auto nibof = [&](int row, float4 v) -> unsigned {
            if (!ldok || row < 0 || row >= HW) return 0xFu;
            return (v.x == 0.f ? 1u : 0u) | (v.y == 0.f ? 2u : 0u) |
                   (v.z == 0.f ? 4u : 0u) | (v.w == 0.f ? 8u : 0u);
        };

        int cnt0 = 0;
        float4 va = vget(r0 - 1);
        float4 vb = vget(r0);
        float4 vnext = vget(r0 + 1);
        unsigned zpm = zprow_calc(nibof(r0 - 1, va), l);
        unsigned zpc = zprow_calc(nibof(r0, vb), l);

        for (int r = r0; r < r0 + 14; r++) {
            float4 vd = vget(r + 2);
            unsigned zpn = zprow_calc(nibof(r + 1, vnext), l);
            unsigned z4 = zpm + zpc + zpn;   // byte-SIMD (max 9/byte)
            if (l < 28) {
                if (z4 == 0) cnt0 += 4;
                else {
                    #pragma unroll
                    for (int j = 0; j < 4; j++) {
                        unsigned bz = (z4 >> (8 * j)) & 0xFFu;
                        if (bz == 0) cnt0++;
                        else atomicAdd(&sbin[bz], 1);
                    }
                }
            }
            zpm = zpc; zpc = zpn; vnext = vd;
        }
        if (l < 28 && cnt0) atomicAdd(&sbin[0], cnt0);
    } else {
        bool wz[KK];
        #pragma unroll
        for (int k = 0; k < KK; k++) wz[k] = (__ldg(&w[c * KK + k]) == 0.0f);
        const int col = tid;
        const int r0q = rc * 56;
        if (col < HW) {
            for (int row = r0q; row < r0q + 56; row++) {
                int z = 0;
                #pragma unroll
                for (int kh = 0; kh < 3; kh++)
                    #pragma unroll
                    for (int kw = 0; kw < 3; kw++) {
                        int gy = row + kh - 1, gx = col + kw - 1;
                        bool zero = (gy < 0 || gy >= HW || gx < 0 || gx >= HW)
                            ? true
                            : (wz[kh * 3 + kw] || __ldg(&xp[gy * HW + gx]) == 0.0f);
                        z += zero ? 1 : 0;
                    }
                atomicAdd(&sbin[z], 1);
            }
        }
    }

    __syncthreads();
    if (tid < NBINS && sbin[tid])
        atomicAdd(&out_hist[c * NBINS + tid], (float)sbin[tid]);
}

// no-op launch-padding kernel: aligns ncu's "-s 5 -c 1" onto the conv kernel
__global__ void nop_kernel() {}

// ---------------------------------------------------------------------------
extern "C" void kernel_launch(void* const* d_in, const int* in_sizes, int n_in,
                              void* d_out, int out_size) {
    const float* x    = (const float*)d_in[0];   // (4,64,224,224)
    const float* wgt  = (const float*)d_in[1];   // (64,64,3,3)
    const float* bias = (const float*)d_in[2];   // (64,)
    float* y    = (float*)d_out;
    float* hist = (float*)d_out + (size_t)Y_ELEMS;

    repack_w_kernel<<<(18 * 8 * 32 * 4 + 255) / 256, 256>>>(wgt, hist);
    conv_mma_kernel<<<NCONV, 256>>>(x, bias, y);
    hist_count_kernel<<<BATCH * CIN * 4, 256>>>(x, wgt, hist);
    nop_kernel<<<1, 32>>>();   // pads launch count so ncu lands on conv
}